// round 3
// baseline (speedup 1.0000x reference)
#include <cuda_runtime.h>

#define Hh 128
#define Ww 128
#define Cc 256
#define Bb 4
#define HW (Hh*Ww)            // 16384
#define TOTAL (Bb*Cc*HW)      // 16777216

__device__ float g_feat1[TOTAL];   // scratch: feat1 = conv1x1(x)
__device__ float g_scale[Cc];
__device__ float g_shift[Cc];

// ---------------------------------------------------------------------------
// Kernel 1: GEMM  feat1[b][o][p] = sum_c W1[o][c]*x[b][c][p] + b1[o]
// BM=128, BN=128, BK=16, 256 threads, 8x8 per thread, packed f32x2 FMA.
// ---------------------------------------------------------------------------
#define BM 128
#define BN 128
#define BK 16

__device__ __forceinline__ unsigned long long fma2(unsigned long long a,
                                                   unsigned long long b,
                                                   unsigned long long c) {
    unsigned long long d;
    asm("fma.rn.f32x2 %0, %1, %2, %3;" : "=l"(d) : "l"(a), "l"(b), "l"(c));
    return d;
}
__device__ __forceinline__ unsigned long long dup2(float a) {
    unsigned long long d;
    asm("mov.b64 %0, {%1, %1};" : "=l"(d) : "r"(__float_as_uint(a)));
    return d;
}

__global__ __launch_bounds__(256, 2)
void gemm_kernel(const float* __restrict__ x,
                 const float* __restrict__ W1,
                 const float* __restrict__ b1) {
    const int b  = blockIdx.z;
    const int m0 = blockIdx.y * BM;
    const int p0 = blockIdx.x * BN;
    const float* xb = x + (size_t)b * Cc * HW;
    float* fb = g_feat1 + (size_t)b * Cc * HW;

    __shared__ float As[BK][BM];   // As[k][m]
    __shared__ float Bs[BK][BN];   // Bs[k][n]

    const int tid = threadIdx.x;
    const int tx = tid & 15, ty = tid >> 4;
    const int mb = ty * 8, nb = tx * 8;

    unsigned long long acc[8][4];
#pragma unroll
    for (int m = 0; m < 8; m++)
#pragma unroll
        for (int j = 0; j < 4; j++) acc[m][j] = 0ULL;

    for (int c0 = 0; c0 < Cc; c0 += BK) {
        // stage A (transpose W1 tile): 128 rows x 16 k
#pragma unroll
        for (int i = 0; i < 2; i++) {
            int v  = tid + i * 256;          // 0..511
            int m  = v >> 2;                 // 0..127
            int kq = (v & 3) << 2;           // 0,4,8,12
            float4 a = *(const float4*)&W1[(size_t)(m0 + m) * Cc + c0 + kq];
            As[kq + 0][m] = a.x;
            As[kq + 1][m] = a.y;
            As[kq + 2][m] = a.z;
            As[kq + 3][m] = a.w;
        }
        // stage B: 16 k x 128 pixels
#pragma unroll
        for (int i = 0; i < 2; i++) {
            int v  = tid + i * 256;
            int k  = v >> 5;                 // 0..15
            int nq = (v & 31) << 2;          // 0..124
            *(float4*)&Bs[k][nq] =
                *(const float4*)&xb[(size_t)(c0 + k) * HW + p0 + nq];
        }
        __syncthreads();

#pragma unroll
        for (int k = 0; k < BK; k++) {
            float4 a0 = *(const float4*)&As[k][mb];
            float4 a1 = *(const float4*)&As[k][mb + 4];
            ulonglong2 bl = *(const ulonglong2*)&Bs[k][nb];
            ulonglong2 bh = *(const ulonglong2*)&Bs[k][nb + 4];
            unsigned long long bv[4] = {bl.x, bl.y, bh.x, bh.y};
            float av[8] = {a0.x, a0.y, a0.z, a0.w, a1.x, a1.y, a1.z, a1.w};
#pragma unroll
            for (int m = 0; m < 8; m++) {
                unsigned long long am = dup2(av[m]);
#pragma unroll
                for (int j = 0; j < 4; j++) acc[m][j] = fma2(am, bv[j], acc[m][j]);
            }
        }
        __syncthreads();
    }

    // epilogue: add bias, store
#pragma unroll
    for (int m = 0; m < 8; m++) {
        int row = m0 + mb + m;
        float bias = b1[row];
        float o[8];
#pragma unroll
        for (int j = 0; j < 4; j++) {
            o[2 * j + 0] = __uint_as_float((unsigned)(acc[m][j] & 0xffffffffULL)) + bias;
            o[2 * j + 1] = __uint_as_float((unsigned)(acc[m][j] >> 32)) + bias;
        }
        float* op = fb + (size_t)row * HW + p0 + nb;
        *(float4*)op       = make_float4(o[0], o[1], o[2], o[3]);
        *(float4*)(op + 4) = make_float4(o[4], o[5], o[6], o[7]);
    }
}

// ---------------------------------------------------------------------------
// Kernel 2: neighbor L1-dist -> softmax -> weighted aggregation + residual
// block = (2 rows x 128 cols) of one (b, h-tile); 256 threads, 1 px/thread.
// Two channel passes, 4 channels staged per barrier.
// OFFS order: (-1,-1),(-1,0),(-1,1),(0,-1),(0,1),(1,-1),(1,0),(1,1)
// ---------------------------------------------------------------------------
#define CH 4

__global__ __launch_bounds__(256)
void agg_kernel(const float* __restrict__ x,
                const float* __restrict__ rp,
                float* __restrict__ out) {
    const int b   = blockIdx.y;
    const int h0  = blockIdx.x * 2;
    const int tid = threadIdx.x;
    const int ty  = tid >> 7;          // 0..1
    const int w   = tid & 127;
    const int h   = h0 + ty;
    const float* fb = g_feat1 + (size_t)b * Cc * HW;

    __shared__ float s[CH][4][Ww];

    int gh[4];
#pragma unroll
    for (int r = 0; r < 4; r++) {
        int hh = h0 - 1 + r;
        gh[r] = min(max(hh, 0), Hh - 1);
    }
    const int wl = max(w - 1, 0), wr = min(w + 1, Ww - 1);

    float dist[8];
#pragma unroll
    for (int k = 0; k < 8; k++) dist[k] = 0.f;

    // ---- pass 1: L1 distances over channels ----
    for (int c0 = 0; c0 < Cc; c0 += CH) {
#pragma unroll
        for (int j = 0; j < 8; j++) {
            int idx = tid + j * 256;
            int col = idx & 127;
            int row = (idx >> 7) & 3;
            int ch  = idx >> 9;
            s[ch][row][col] = fb[(size_t)(c0 + ch) * HW + gh[row] * Ww + col];
        }
        __syncthreads();
#pragma unroll
        for (int ch = 0; ch < CH; ch++) {
            float f0 = s[ch][ty + 1][w];
            dist[0] += fabsf(f0 - s[ch][ty    ][wl]);
            dist[1] += fabsf(f0 - s[ch][ty    ][w ]);
            dist[2] += fabsf(f0 - s[ch][ty    ][wr]);
            dist[3] += fabsf(f0 - s[ch][ty + 1][wl]);
            dist[4] += fabsf(f0 - s[ch][ty + 1][wr]);
            dist[5] += fabsf(f0 - s[ch][ty + 2][wl]);
            dist[6] += fabsf(f0 - s[ch][ty + 2][w ]);
            dist[7] += fabsf(f0 - s[ch][ty + 2][wr]);
        }
        __syncthreads();
    }

    // ---- softmax(-r * dist) over 8 neighbors ----
    const float rv = rp[0];
    float mx = -rv * dist[0];
#pragma unroll
    for (int k = 1; k < 8; k++) mx = fmaxf(mx, -rv * dist[k]);
    float m[8];
    float sum = 0.f;
#pragma unroll
    for (int k = 0; k < 8; k++) {
        m[k] = exp2f((-rv * dist[k] - mx) * 1.4426950408889634f);
        sum += m[k];
    }
    const float inv = 1.f / sum;
#pragma unroll
    for (int k = 0; k < 8; k++) m[k] *= inv;

    // ---- pass 2: weighted aggregation + residual ----
    const size_t pix = (size_t)b * Cc * HW + (size_t)h * Ww + w;
    for (int c0 = 0; c0 < Cc; c0 += CH) {
#pragma unroll
        for (int j = 0; j < 8; j++) {
            int idx = tid + j * 256;
            int col = idx & 127;
            int row = (idx >> 7) & 3;
            int ch  = idx >> 9;
            s[ch][row][col] = fb[(size_t)(c0 + ch) * HW + gh[row] * Ww + col];
        }
        __syncthreads();
#pragma unroll
        for (int ch = 0; ch < CH; ch++) {
            float a;
            a = m[0] * s[ch][ty    ][wl];
            a = fmaf(m[1], s[ch][ty    ][w ], a);
            a = fmaf(m[2], s[ch][ty    ][wr], a);
            a = fmaf(m[3], s[ch][ty + 1][wl], a);
            a = fmaf(m[4], s[ch][ty + 1][wr], a);
            a = fmaf(m[5], s[ch][ty + 2][wl], a);
            a = fmaf(m[6], s[ch][ty + 2][w ], a);
            a = fmaf(m[7], s[ch][ty + 2][wr], a);
            size_t off = pix + (size_t)(c0 + ch) * HW;
            out[off] = a + x[off];
        }
        __syncthreads();
    }
}

// ---------------------------------------------------------------------------
// Kernel 3: per-channel batch statistics -> scale/shift (1 block / channel)
// ---------------------------------------------------------------------------
__global__ __launch_bounds__(256)
void stats_kernel(const float* __restrict__ out,
                  const float* __restrict__ gamma,
                  const float* __restrict__ beta) {
    const int c = blockIdx.x;
    const int tid = threadIdx.x;
    float sum = 0.f, sq = 0.f;
#pragma unroll
    for (int b = 0; b < Bb; b++) {
        const float4* p = (const float4*)(out + ((size_t)b * Cc + c) * HW);
        for (int i = tid; i < HW / 4; i += 256) {
            float4 v = p[i];
            sum += (v.x + v.y) + (v.z + v.w);
            sq = fmaf(v.x, v.x, sq);
            sq = fmaf(v.y, v.y, sq);
            sq = fmaf(v.z, v.z, sq);
            sq = fmaf(v.w, v.w, sq);
        }
    }
    __shared__ float s1[8], s2[8];
    int lane = tid & 31, wid = tid >> 5;
#pragma unroll
    for (int o = 16; o > 0; o >>= 1) {
        sum += __shfl_xor_sync(0xffffffff, sum, o);
        sq  += __shfl_xor_sync(0xffffffff, sq, o);
    }
    if (lane == 0) { s1[wid] = sum; s2[wid] = sq; }
    __syncthreads();
    if (tid == 0) {
        float S = 0.f, Q = 0.f;
#pragma unroll
        for (int i = 0; i < 8; i++) { S += s1[i]; Q += s2[i]; }
        const float n = (float)(Bb * HW);
        float mean = S / n;
        float var  = Q / n - mean * mean;
        float istd = rsqrtf(var + 1e-5f);
        float sc   = istd * gamma[c];
        g_scale[c] = sc;
        g_shift[c] = beta[c] - mean * sc;
    }
}

// ---------------------------------------------------------------------------
// Kernel 4: in-place BN apply + LeakyReLU
// ---------------------------------------------------------------------------
__global__ __launch_bounds__(256)
void bnact_kernel(float* __restrict__ out) {
    int i4 = blockIdx.x * 256 + threadIdx.x;     // float4 index
    int c  = ((i4 * 4) >> 14) & (Cc - 1);
    float sc = g_scale[c], sh = g_shift[c];
    float4 v = ((float4*)out)[i4];
    v.x = fmaf(v.x, sc, sh); v.x = fmaxf(v.x, 0.01f * v.x);
    v.y = fmaf(v.y, sc, sh); v.y = fmaxf(v.y, 0.01f * v.y);
    v.z = fmaf(v.z, sc, sh); v.z = fmaxf(v.z, 0.01f * v.z);
    v.w = fmaf(v.w, sc, sh); v.w = fmaxf(v.w, 0.01f * v.w);
    ((float4*)out)[i4] = v;
}

// ---------------------------------------------------------------------------
extern "C" void kernel_launch(void* const* d_in, const int* in_sizes, int n_in,
                              void* d_out, int out_size) {
    const float* x     = (const float*)d_in[0];
    const float* W1    = (const float*)d_in[1];
    const float* b1    = (const float*)d_in[2];
    const float* r     = (const float*)d_in[3];
    const float* gamma = (const float*)d_in[4];
    const float* beta  = (const float*)d_in[5];
    float* out = (float*)d_out;

    // 1) feat1 = W1 @ x + b1
    gemm_kernel<<<dim3(HW / BN, Cc / BM, Bb), 256>>>(x, W1, b1);
    // 2) neighbor softmax aggregation + residual (pre-BN) -> out
    agg_kernel<<<dim3(Hh / 2, Bb), 256>>>(x, r, out);
    // 3) batch statistics per channel
    stats_kernel<<<Cc, 256>>>(out, gamma, beta);
    // 4) BN + LeakyReLU in place
    bnact_kernel<<<TOTAL / 4 / 256, 256>>>(out);
}

// round 14
// speedup vs baseline: 1.3253x; 1.3253x over previous
#include <cuda_runtime.h>
#include <cuda_bf16.h>
#include <cstdint>

#define Hh 128
#define Ww 128
#define Cc 256
#define Bb 4
#define HW (Hh*Ww)            // 16384
#define TOTAL (Bb*Cc*HW)      // 16777216

__device__ float g_feat1[TOTAL];               // feat1 = conv1x1(x), fp32 [b][c][p]
__device__ __nv_bfloat16 g_xt_hi[TOTAL];       // x transposed+split: [b][p][c]
__device__ __nv_bfloat16 g_xt_lo[TOTAL];
__device__ __nv_bfloat16 g_Whi[Cc*Cc];         // bf16 split of W1 [o][c]
__device__ __nv_bfloat16 g_Wlo[Cc*Cc];
__device__ float g_scale[Cc];
__device__ float g_shift[Cc];

// ---------------------------------------------------------------------------
// helpers (baseline PTX only — no sm_103a-accelerated features)
// ---------------------------------------------------------------------------
__device__ __forceinline__ uint32_t smem_u32(const void* p) {
    uint32_t a;
    asm("{ .reg .u64 t; cvta.to.shared.u64 t, %1; cvt.u32.u64 %0, t; }"
        : "=r"(a) : "l"(p));
    return a;
}
__device__ __forceinline__ void cp_async16(uint32_t dst, const void* src) {
    asm volatile("cp.async.cg.shared.global [%0], [%1], 16;"
                 :: "r"(dst), "l"(src) : "memory");
}
__device__ __forceinline__ void mma16816(float* d, const uint32_t* a,
                                         const uint32_t* b) {
    asm volatile(
        "mma.sync.aligned.m16n8k16.row.col.f32.bf16.bf16.f32 "
        "{%0,%1,%2,%3}, {%4,%5,%6,%7}, {%8,%9}, {%0,%1,%2,%3};"
        : "+f"(d[0]), "+f"(d[1]), "+f"(d[2]), "+f"(d[3])
        : "r"(a[0]), "r"(a[1]), "r"(a[2]), "r"(a[3]), "r"(b[0]), "r"(b[1]));
}

// ---------------------------------------------------------------------------
// prep_w: bf16 hi/lo split of W1
// ---------------------------------------------------------------------------
__global__ void prep_w_kernel(const float* __restrict__ W1) {
    int i = blockIdx.x * 256 + threadIdx.x;      // 65536 entries
    float w = W1[i];
    __nv_bfloat16 hi = __float2bfloat16_rn(w);
    __nv_bfloat16 lo = __float2bfloat16_rn(w - __bfloat162float(hi));
    g_Whi[i] = hi;
    g_Wlo[i] = lo;
}

// ---------------------------------------------------------------------------
// prep_x: transpose [b][c][p] -> [b][p][c] and bf16 hi/lo split
// ---------------------------------------------------------------------------
__global__ __launch_bounds__(256)
void prep_x_kernel(const float* __restrict__ x) {
    __shared__ float s[32][33];
    const int b  = blockIdx.z;
    const int c0 = blockIdx.y * 32;
    const int p0 = blockIdx.x * 32;
    const int tx = threadIdx.x, ty = threadIdx.y;
#pragma unroll
    for (int i = 0; i < 4; i++) {
        int c = ty + i * 8;
        s[c][tx] = x[((size_t)b * Cc + c0 + c) * HW + p0 + tx];
    }
    __syncthreads();
#pragma unroll
    for (int i = 0; i < 4; i++) {
        int p = ty + i * 8;
        float v = s[tx][p];
        __nv_bfloat16 hi = __float2bfloat16_rn(v);
        __nv_bfloat16 lo = __float2bfloat16_rn(v - __bfloat162float(hi));
        size_t off = ((size_t)b * HW + p0 + p) * Cc + c0 + tx;
        g_xt_hi[off] = hi;
        g_xt_lo[off] = lo;
    }
}

// ---------------------------------------------------------------------------
// GEMM via mma.sync bf16 3-product split (HMMA), fp32 accumulate in regs.
// CTA tile: M=128 (out-ch) x N=128 (pixels).  K=256 in 8 chunks of 32.
// 8 warps, warp tile 32x64 (2 m-tiles x 8 n-tiles of 16x8).
// smem per buffer: 4 tiles (A_hi, A_lo, B_hi, B_lo) of 128 rows x 32 bf16,
// rows padded to 40 bf16 (80B) -> conflict-free fragment loads.
// Double-buffered cp.async.
// ---------------------------------------------------------------------------
#define ROWB   80                   // padded row bytes (40 bf16)
#define TILEB  (128*ROWB)           // 10240 B per tile
#define BUFB   (4*TILEB)            // 40960 B per buffer
#define GSMEM  (2*BUFB)             // 81920 B total

__global__ __launch_bounds__(256, 2)
void gemm_mma_kernel(const float* __restrict__ b1) {
    extern __shared__ char smc[];
    const uint32_t sbase = smem_u32(smc);
    const int tid  = threadIdx.x;
    const int wid  = tid >> 5, lane = tid & 31;
    const int gid  = lane >> 2, tg = lane & 3;
    const int p0   = blockIdx.x * 128;
    const int m0   = blockIdx.y * 128;
    const int b    = blockIdx.z;
    const int mrow = (wid >> 1) * 32;
    const int ncol = (wid & 1) * 64;

    float acc[2][8][4];
#pragma unroll
    for (int mt = 0; mt < 2; mt++)
#pragma unroll
        for (int nt = 0; nt < 8; nt++)
#pragma unroll
            for (int j = 0; j < 4; j++) acc[mt][nt][j] = 0.f;

    // ---- stage one K-chunk (32 k) of all 4 tiles into buffer `buf` ----
    auto stage = [&](int kc, int buf) {
        uint32_t bb = sbase + buf * BUFB;
        const int cidx0 = kc * 32;
#pragma unroll
        for (int it = 0; it < 8; it++) {
            int id  = tid + it * 256;            // 0..2047
            int t   = id >> 9;                   // tile 0..3
            int row = (id >> 2) & 127;
            int seg = id & 3;                    // 16B segment
            uint32_t dst = bb + t * TILEB + row * ROWB + seg * 16;
            int cidx = cidx0 + seg * 8;
            const __nv_bfloat16* src;
            if (t == 0)      src = g_Whi  + (size_t)(m0 + row) * Cc + cidx;
            else if (t == 1) src = g_Wlo  + (size_t)(m0 + row) * Cc + cidx;
            else if (t == 2) src = g_xt_hi + ((size_t)b * HW + p0 + row) * Cc + cidx;
            else             src = g_xt_lo + ((size_t)b * HW + p0 + row) * Cc + cidx;
            cp_async16(dst, src);
        }
        asm volatile("cp.async.commit_group;" ::: "memory");
    };

    stage(0, 0);

    for (int kc = 0; kc < 8; kc++) {
        if (kc < 7) stage(kc + 1, (kc + 1) & 1);
        if (kc < 7) asm volatile("cp.async.wait_group 1;" ::: "memory");
        else        asm volatile("cp.async.wait_group 0;" ::: "memory");
        __syncthreads();

        const char* base = smc + (kc & 1) * BUFB;
#pragma unroll
        for (int s = 0; s < 2; s++) {
            const int kb = s * 32;               // byte offset of k16 step
            uint32_t ah[2][4], al[2][4];
#pragma unroll
            for (int mt = 0; mt < 2; mt++) {
                const char* ap = base + (mrow + mt * 16 + gid) * ROWB + kb + tg * 4;
                ah[mt][0] = *(const uint32_t*)(ap);
                ah[mt][1] = *(const uint32_t*)(ap + 8 * ROWB);
                ah[mt][2] = *(const uint32_t*)(ap + 16);
                ah[mt][3] = *(const uint32_t*)(ap + 8 * ROWB + 16);
                const char* ap2 = ap + TILEB;    // A_lo tile
                al[mt][0] = *(const uint32_t*)(ap2);
                al[mt][1] = *(const uint32_t*)(ap2 + 8 * ROWB);
                al[mt][2] = *(const uint32_t*)(ap2 + 16);
                al[mt][3] = *(const uint32_t*)(ap2 + 8 * ROWB + 16);
            }
#pragma unroll
            for (int nt = 0; nt < 8; nt++) {
                const char* bp = base + 2 * TILEB +
                                 (ncol + nt * 8 + gid) * ROWB + kb + tg * 4;
                uint32_t bh[2], bl[2];
                bh[0] = *(const uint32_t*)(bp);
                bh[1] = *(const uint32_t*)(bp + 16);
                mma16816(acc[0][nt], ah[0], bh);
                mma16816(acc[1][nt], ah[1], bh);
                mma16816(acc[0][nt], al[0], bh);
                mma16816(acc[1][nt], al[1], bh);
                const char* bp2 = bp + TILEB;    // B_lo tile
                bl[0] = *(const uint32_t*)(bp2);
                bl[1] = *(const uint32_t*)(bp2 + 16);
                mma16816(acc[0][nt], ah[0], bl);
                mma16816(acc[1][nt], ah[1], bl);
            }
        }
        __syncthreads();
    }

    // ---- epilogue: bias + store ----
#pragma unroll
    for (int mt = 0; mt < 2; mt++) {
        int r0 = m0 + mrow + mt * 16 + gid;
        int r1 = r0 + 8;
        float bias0 = b1[r0], bias1 = b1[r1];
        float* o0 = g_feat1 + ((size_t)b * Cc + r0) * HW + p0 + ncol + tg * 2;
        float* o1 = g_feat1 + ((size_t)b * Cc + r1) * HW + p0 + ncol + tg * 2;
#pragma unroll
        for (int nt = 0; nt < 8; nt++) {
            float2 v0 = make_float2(acc[mt][nt][0] + bias0, acc[mt][nt][1] + bias0);
            float2 v1 = make_float2(acc[mt][nt][2] + bias1, acc[mt][nt][3] + bias1);
            *(float2*)(o0 + nt * 8) = v0;
            *(float2*)(o1 + nt * 8) = v1;
        }
    }
}

// ---------------------------------------------------------------------------
// Kernel 2: neighbor L1-dist -> softmax -> weighted aggregation + residual
// ---------------------------------------------------------------------------
#define CH 4

__global__ __launch_bounds__(256)
void agg_kernel(const float* __restrict__ x,
                const float* __restrict__ rp,
                float* __restrict__ out) {
    const int b   = blockIdx.y;
    const int h0  = blockIdx.x * 2;
    const int tid = threadIdx.x;
    const int ty  = tid >> 7;
    const int w   = tid & 127;
    const int h   = h0 + ty;
    const float* fb = g_feat1 + (size_t)b * Cc * HW;

    __shared__ float s[CH][4][Ww];

    int gh[4];
#pragma unroll
    for (int r = 0; r < 4; r++) {
        int hh = h0 - 1 + r;
        gh[r] = min(max(hh, 0), Hh - 1);
    }
    const int wl = max(w - 1, 0), wr = min(w + 1, Ww - 1);

    float dist[8];
#pragma unroll
    for (int k = 0; k < 8; k++) dist[k] = 0.f;

    for (int c0 = 0; c0 < Cc; c0 += CH) {
#pragma unroll
        for (int j = 0; j < 8; j++) {
            int idx = tid + j * 256;
            int col = idx & 127;
            int row = (idx >> 7) & 3;
            int ch  = idx >> 9;
            s[ch][row][col] = fb[(size_t)(c0 + ch) * HW + gh[row] * Ww + col];
        }
        __syncthreads();
#pragma unroll
        for (int ch = 0; ch < CH; ch++) {
            float f0 = s[ch][ty + 1][w];
            dist[0] += fabsf(f0 - s[ch][ty    ][wl]);
            dist[1] += fabsf(f0 - s[ch][ty    ][w ]);
            dist[2] += fabsf(f0 - s[ch][ty    ][wr]);
            dist[3] += fabsf(f0 - s[ch][ty + 1][wl]);
            dist[4] += fabsf(f0 - s[ch][ty + 1][wr]);
            dist[5] += fabsf(f0 - s[ch][ty + 2][wl]);
            dist[6] += fabsf(f0 - s[ch][ty + 2][w ]);
            dist[7] += fabsf(f0 - s[ch][ty + 2][wr]);
        }
        __syncthreads();
    }

    const float rv = rp[0];
    float mx = -rv * dist[0];
#pragma unroll
    for (int k = 1; k < 8; k++) mx = fmaxf(mx, -rv * dist[k]);
    float m[8];
    float sum = 0.f;
#pragma unroll
    for (int k = 0; k < 8; k++) {
        m[k] = exp2f((-rv * dist[k] - mx) * 1.4426950408889634f);
        sum += m[k];
    }
    const float inv = 1.f / sum;
#pragma unroll
    for (int k = 0; k < 8; k++) m[k] *= inv;

    const size_t pix = (size_t)b * Cc * HW + (size_t)h * Ww + w;
    for (int c0 = 0; c0 < Cc; c0 += CH) {
#pragma unroll
        for (int j = 0; j < 8; j++) {
            int idx = tid + j * 256;
            int col = idx & 127;
            int row = (idx >> 7) & 3;
            int ch  = idx >> 9;
            s[ch][row][col] = fb[(size_t)(c0 + ch) * HW + gh[row] * Ww + col];
        }
        __syncthreads();
#pragma unroll
        for (int ch = 0; ch < CH; ch++) {
            float a;
            a = m[0] * s[ch][ty    ][wl];
            a = fmaf(m[1], s[ch][ty    ][w ], a);
            a = fmaf(m[2], s[ch][ty    ][wr], a);
            a = fmaf(m[3], s[ch][ty + 1][wl], a);
            a = fmaf(m[4], s[ch][ty + 1][wr], a);
            a = fmaf(m[5], s[ch][ty + 2][wl], a);
            a = fmaf(m[6], s[ch][ty + 2][w ], a);
            a = fmaf(m[7], s[ch][ty + 2][wr], a);
            size_t off = pix + (size_t)(c0 + ch) * HW;
            out[off] = a + x[off];
        }
        __syncthreads();
    }
}

// ---------------------------------------------------------------------------
// Kernel 3: per-channel batch statistics -> scale/shift
// ---------------------------------------------------------------------------
__global__ __launch_bounds__(256)
void stats_kernel(const float* __restrict__ out,
                  const float* __restrict__ gamma,
                  const float* __restrict__ beta) {
    const int c = blockIdx.x;
    const int tid = threadIdx.x;
    float sum = 0.f, sq = 0.f;
#pragma unroll
    for (int b = 0; b < Bb; b++) {
        const float4* p = (const float4*)(out + ((size_t)b * Cc + c) * HW);
        for (int i = tid; i < HW / 4; i += 256) {
            float4 v = p[i];
            sum += (v.x + v.y) + (v.z + v.w);
            sq = fmaf(v.x, v.x, sq);
            sq = fmaf(v.y, v.y, sq);
            sq = fmaf(v.z, v.z, sq);
            sq = fmaf(v.w, v.w, sq);
        }
    }
    __shared__ float s1[8], s2[8];
    int lane = tid & 31, wid = tid >> 5;
#pragma unroll
    for (int o = 16; o > 0; o >>= 1) {
        sum += __shfl_xor_sync(0xffffffff, sum, o);
        sq  += __shfl_xor_sync(0xffffffff, sq, o);
    }
    if (lane == 0) { s1[wid] = sum; s2[wid] = sq; }
    __syncthreads();
    if (tid == 0) {
        float S = 0.f, Q = 0.f;
#pragma unroll
        for (int i = 0; i < 8; i++) { S += s1[i]; Q += s2[i]; }
        const float n = (float)(Bb * HW);
        float mean = S / n;
        float var  = Q / n - mean * mean;
        float istd = rsqrtf(var + 1e-5f);
        float sc   = istd * gamma[c];
        g_scale[c] = sc;
        g_shift[c] = beta[c] - mean * sc;
    }
}

// ---------------------------------------------------------------------------
// Kernel 4: in-place BN apply + LeakyReLU
// ---------------------------------------------------------------------------
__global__ __launch_bounds__(256)
void bnact_kernel(float* __restrict__ out) {
    int i4 = blockIdx.x * 256 + threadIdx.x;
    int c  = ((i4 * 4) >> 14) & (Cc - 1);
    float sc = g_scale[c], sh = g_shift[c];
    float4 v = ((float4*)out)[i4];
    v.x = fmaf(v.x, sc, sh); v.x = fmaxf(v.x, 0.01f * v.x);
    v.y = fmaf(v.y, sc, sh); v.y = fmaxf(v.y, 0.01f * v.y);
    v.z = fmaf(v.z, sc, sh); v.z = fmaxf(v.z, 0.01f * v.z);
    v.w = fmaf(v.w, sc, sh); v.w = fmaxf(v.w, 0.01f * v.w);
    ((float4*)out)[i4] = v;
}

// ---------------------------------------------------------------------------
extern "C" void kernel_launch(void* const* d_in, const int* in_sizes, int n_in,
                              void* d_out, int out_size) {
    const float* x     = (const float*)d_in[0];
    const float* W1    = (const float*)d_in[1];
    const float* b1    = (const float*)d_in[2];
    const float* r     = (const float*)d_in[3];
    const float* gamma = (const float*)d_in[4];
    const float* beta  = (const float*)d_in[5];
    float* out = (float*)d_out;

    cudaFuncSetAttribute(gemm_mma_kernel,
                         cudaFuncAttributeMaxDynamicSharedMemorySize, GSMEM);

    // 0) bf16 splits
    prep_w_kernel<<<Cc * Cc / 256, 256>>>(W1);
    prep_x_kernel<<<dim3(HW / 32, Cc / 32, Bb), dim3(32, 8)>>>(x);
    // 1) feat1 = W1 @ x + b1  (HMMA bf16 3-product)
    gemm_mma_kernel<<<dim3(HW / 128, Cc / 128, Bb), 256, GSMEM>>>(b1);
    // 2) neighbor softmax aggregation + residual (pre-BN) -> out
    agg_kernel<<<dim3(Hh / 2, Bb), 256>>>(x, r, out);
    // 3) batch statistics per channel
    stats_kernel<<<Cc, 256>>>(out, gamma, beta);
    // 4) BN + LeakyReLU in place
    bnact_kernel<<<TOTAL / 4 / 256, 256>>>(out);
}

// round 15
// speedup vs baseline: 1.5402x; 1.1621x over previous
#include <cuda_runtime.h>
#include <cuda_bf16.h>
#include <cstdint>

#define Hh 128
#define Ww 128
#define Cc 256
#define Bb 4
#define HW (Hh*Ww)            // 16384
#define TOTAL (Bb*Cc*HW)      // 16777216
#define NPIX (Bb*HW)          // 65536
#define CS 8                  // channel splits
#define CPS (Cc/CS)           // 32 channels per split

__device__ float g_feat1[TOTAL];               // feat1 = conv1x1(x), fp32 [b][c][p]
__device__ __nv_bfloat16 g_xt_hi[TOTAL];       // x transposed+split: [b][p][c]
__device__ __nv_bfloat16 g_xt_lo[TOTAL];
__device__ __nv_bfloat16 g_Whi[Cc*Cc];         // bf16 split of W1 [o][c]
__device__ __nv_bfloat16 g_Wlo[Cc*Cc];
__device__ float g_dp[CS*8*NPIX];              // partial L1 dists [cs][k][pix]
__device__ float g_m[8*NPIX];                  // softmax weights [k][pix]
__device__ float g_scale[Cc];
__device__ float g_shift[Cc];

// ---------------------------------------------------------------------------
// helpers (baseline PTX only)
// ---------------------------------------------------------------------------
__device__ __forceinline__ uint32_t smem_u32(const void* p) {
    uint32_t a;
    asm("{ .reg .u64 t; cvta.to.shared.u64 t, %1; cvt.u32.u64 %0, t; }"
        : "=r"(a) : "l"(p));
    return a;
}
__device__ __forceinline__ void cp_async16(uint32_t dst, const void* src) {
    asm volatile("cp.async.cg.shared.global [%0], [%1], 16;"
                 :: "r"(dst), "l"(src) : "memory");
}
__device__ __forceinline__ void mma16816(float* d, const uint32_t* a,
                                         const uint32_t* b) {
    asm volatile(
        "mma.sync.aligned.m16n8k16.row.col.f32.bf16.bf16.f32 "
        "{%0,%1,%2,%3}, {%4,%5,%6,%7}, {%8,%9}, {%0,%1,%2,%3};"
        : "+f"(d[0]), "+f"(d[1]), "+f"(d[2]), "+f"(d[3])
        : "r"(a[0]), "r"(a[1]), "r"(a[2]), "r"(a[3]), "r"(b[0]), "r"(b[1]));
}

// ---------------------------------------------------------------------------
// prep_w: bf16 hi/lo split of W1
// ---------------------------------------------------------------------------
__global__ void prep_w_kernel(const float* __restrict__ W1) {
    int i = blockIdx.x * 256 + threadIdx.x;
    float w = W1[i];
    __nv_bfloat16 hi = __float2bfloat16_rn(w);
    __nv_bfloat16 lo = __float2bfloat16_rn(w - __bfloat162float(hi));
    g_Whi[i] = hi;
    g_Wlo[i] = lo;
}

// ---------------------------------------------------------------------------
// prep_x: transpose [b][c][p] -> [b][p][c] and bf16 hi/lo split
// ---------------------------------------------------------------------------
__global__ __launch_bounds__(256)
void prep_x_kernel(const float* __restrict__ x) {
    __shared__ float s[32][33];
    const int b  = blockIdx.z;
    const int c0 = blockIdx.y * 32;
    const int p0 = blockIdx.x * 32;
    const int tx = threadIdx.x, ty = threadIdx.y;
#pragma unroll
    for (int i = 0; i < 4; i++) {
        int c = ty + i * 8;
        s[c][tx] = x[((size_t)b * Cc + c0 + c) * HW + p0 + tx];
    }
    __syncthreads();
#pragma unroll
    for (int i = 0; i < 4; i++) {
        int p = ty + i * 8;
        float v = s[tx][p];
        __nv_bfloat16 hi = __float2bfloat16_rn(v);
        __nv_bfloat16 lo = __float2bfloat16_rn(v - __bfloat162float(hi));
        size_t off = ((size_t)b * HW + p0 + p) * Cc + c0 + tx;
        g_xt_hi[off] = hi;
        g_xt_lo[off] = lo;
    }
}

// ---------------------------------------------------------------------------
// GEMM via mma.sync bf16 3-product split (HMMA), fp32 accumulate in regs.
// (unchanged from R14-winning version)
// ---------------------------------------------------------------------------
#define ROWB   80
#define TILEB  (128*ROWB)
#define BUFB   (4*TILEB)
#define GSMEM  (2*BUFB)

__global__ __launch_bounds__(256, 2)
void gemm_mma_kernel(const float* __restrict__ b1) {
    extern __shared__ char smc[];
    const uint32_t sbase = smem_u32(smc);
    const int tid  = threadIdx.x;
    const int wid  = tid >> 5, lane = tid & 31;
    const int gid  = lane >> 2, tg = lane & 3;
    const int p0   = blockIdx.x * 128;
    const int m0   = blockIdx.y * 128;
    const int b    = blockIdx.z;
    const int mrow = (wid >> 1) * 32;
    const int ncol = (wid & 1) * 64;

    float acc[2][8][4];
#pragma unroll
    for (int mt = 0; mt < 2; mt++)
#pragma unroll
        for (int nt = 0; nt < 8; nt++)
#pragma unroll
            for (int j = 0; j < 4; j++) acc[mt][nt][j] = 0.f;

    auto stage = [&](int kc, int buf) {
        uint32_t bb = sbase + buf * BUFB;
        const int cidx0 = kc * 32;
#pragma unroll
        for (int it = 0; it < 8; it++) {
            int id  = tid + it * 256;
            int t   = id >> 9;
            int row = (id >> 2) & 127;
            int seg = id & 3;
            uint32_t dst = bb + t * TILEB + row * ROWB + seg * 16;
            int cidx = cidx0 + seg * 8;
            const __nv_bfloat16* src;
            if (t == 0)      src = g_Whi  + (size_t)(m0 + row) * Cc + cidx;
            else if (t == 1) src = g_Wlo  + (size_t)(m0 + row) * Cc + cidx;
            else if (t == 2) src = g_xt_hi + ((size_t)b * HW + p0 + row) * Cc + cidx;
            else             src = g_xt_lo + ((size_t)b * HW + p0 + row) * Cc + cidx;
            cp_async16(dst, src);
        }
        asm volatile("cp.async.commit_group;" ::: "memory");
    };

    stage(0, 0);

    for (int kc = 0; kc < 8; kc++) {
        if (kc < 7) stage(kc + 1, (kc + 1) & 1);
        if (kc < 7) asm volatile("cp.async.wait_group 1;" ::: "memory");
        else        asm volatile("cp.async.wait_group 0;" ::: "memory");
        __syncthreads();

        const char* base = smc + (kc & 1) * BUFB;
#pragma unroll
        for (int s = 0; s < 2; s++) {
            const int kb = s * 32;
            uint32_t ah[2][4], al[2][4];
#pragma unroll
            for (int mt = 0; mt < 2; mt++) {
                const char* ap = base + (mrow + mt * 16 + gid) * ROWB + kb + tg * 4;
                ah[mt][0] = *(const uint32_t*)(ap);
                ah[mt][1] = *(const uint32_t*)(ap + 8 * ROWB);
                ah[mt][2] = *(const uint32_t*)(ap + 16);
                ah[mt][3] = *(const uint32_t*)(ap + 8 * ROWB + 16);
                const char* ap2 = ap + TILEB;
                al[mt][0] = *(const uint32_t*)(ap2);
                al[mt][1] = *(const uint32_t*)(ap2 + 8 * ROWB);
                al[mt][2] = *(const uint32_t*)(ap2 + 16);
                al[mt][3] = *(const uint32_t*)(ap2 + 8 * ROWB + 16);
            }
#pragma unroll
            for (int nt = 0; nt < 8; nt++) {
                const char* bp = base + 2 * TILEB +
                                 (ncol + nt * 8 + gid) * ROWB + kb + tg * 4;
                uint32_t bh[2], bl[2];
                bh[0] = *(const uint32_t*)(bp);
                bh[1] = *(const uint32_t*)(bp + 16);
                mma16816(acc[0][nt], ah[0], bh);
                mma16816(acc[1][nt], ah[1], bh);
                mma16816(acc[0][nt], al[0], bh);
                mma16816(acc[1][nt], al[1], bh);
                const char* bp2 = bp + TILEB;
                bl[0] = *(const uint32_t*)(bp2);
                bl[1] = *(const uint32_t*)(bp2 + 16);
                mma16816(acc[0][nt], ah[0], bl);
                mma16816(acc[1][nt], ah[1], bl);
            }
        }
        __syncthreads();
    }

#pragma unroll
    for (int mt = 0; mt < 2; mt++) {
        int r0 = m0 + mrow + mt * 16 + gid;
        int r1 = r0 + 8;
        float bias0 = b1[r0], bias1 = b1[r1];
        float* o0 = g_feat1 + ((size_t)b * Cc + r0) * HW + p0 + ncol + tg * 2;
        float* o1 = g_feat1 + ((size_t)b * Cc + r1) * HW + p0 + ncol + tg * 2;
#pragma unroll
        for (int nt = 0; nt < 8; nt++) {
            float2 v0 = make_float2(acc[mt][nt][0] + bias0, acc[mt][nt][1] + bias0);
            float2 v1 = make_float2(acc[mt][nt][2] + bias1, acc[mt][nt][3] + bias1);
            *(float2*)(o0 + nt * 8) = v0;
            *(float2*)(o1 + nt * 8) = v1;
        }
    }
}

// ---------------------------------------------------------------------------
// Kernel 2a: partial L1 distances, barrier-free, channel-split.
// grid (Hh/8, Bb, CS), block 256 = 8 rows x 32 lanes; 4 px/thread via float4.
// OFFS: 0:(-1,-1) 1:(-1,0) 2:(-1,1) 3:(0,-1) 4:(0,1) 5:(1,-1) 6:(1,0) 7:(1,1)
// ---------------------------------------------------------------------------
__global__ __launch_bounds__(256)
void dist_kernel() {
    const int b    = blockIdx.y;
    const int cs   = blockIdx.z;
    const int h    = blockIdx.x * 8 + (threadIdx.x >> 5);
    const int lane = threadIdx.x & 31;
    const int hm = max(h - 1, 0), hp = min(h + 1, Hh - 1);
    const float* fb = g_feat1 + ((size_t)b * Cc + cs * CPS) * HW;

    float d[8][4];
#pragma unroll
    for (int k = 0; k < 8; k++)
#pragma unroll
        for (int i = 0; i < 4; i++) d[k][i] = 0.f;

#pragma unroll 2
    for (int c = 0; c < CPS; c++) {
        const float* pl = fb + (size_t)c * HW;
        float4 vm = *(const float4*)(pl + hm * Ww + lane * 4);
        float4 v0 = *(const float4*)(pl + h  * Ww + lane * 4);
        float4 vp = *(const float4*)(pl + hp * Ww + lane * 4);
        float lm = __shfl_up_sync(0xffffffffu, vm.w, 1); if (lane == 0) lm = vm.x;
        float l0 = __shfl_up_sync(0xffffffffu, v0.w, 1); if (lane == 0) l0 = v0.x;
        float lp = __shfl_up_sync(0xffffffffu, vp.w, 1); if (lane == 0) lp = vp.x;
        float rm = __shfl_down_sync(0xffffffffu, vm.x, 1); if (lane == 31) rm = vm.w;
        float r0 = __shfl_down_sync(0xffffffffu, v0.x, 1); if (lane == 31) r0 = v0.w;
        float rp = __shfl_down_sync(0xffffffffu, vp.x, 1); if (lane == 31) rp = vp.w;
        float tm[6] = {lm, vm.x, vm.y, vm.z, vm.w, rm};
        float t0[6] = {l0, v0.x, v0.y, v0.z, v0.w, r0};
        float tp[6] = {lp, vp.x, vp.y, vp.z, vp.w, rp};
#pragma unroll
        for (int i = 0; i < 4; i++) {
            float f0 = t0[i + 1];
            d[0][i] += fabsf(f0 - tm[i]);
            d[1][i] += fabsf(f0 - tm[i + 1]);
            d[2][i] += fabsf(f0 - tm[i + 2]);
            d[3][i] += fabsf(f0 - t0[i]);
            d[4][i] += fabsf(f0 - t0[i + 2]);
            d[5][i] += fabsf(f0 - tp[i]);
            d[6][i] += fabsf(f0 - tp[i + 1]);
            d[7][i] += fabsf(f0 - tp[i + 2]);
        }
    }

    const size_t pix = (size_t)b * HW + h * Ww + lane * 4;
#pragma unroll
    for (int k = 0; k < 8; k++) {
        *(float4*)&g_dp[((size_t)(cs * 8 + k)) * NPIX + pix] =
            make_float4(d[k][0], d[k][1], d[k][2], d[k][3]);
    }
}

// ---------------------------------------------------------------------------
// Kernel 2b: reduce partials over CS, softmax -> weights m[k][pix]
// ---------------------------------------------------------------------------
__global__ __launch_bounds__(256)
void weights_kernel(const float* __restrict__ rp) {
    const int pix = blockIdx.x * 256 + threadIdx.x;
    float dist[8];
#pragma unroll
    for (int k = 0; k < 8; k++) dist[k] = 0.f;
#pragma unroll
    for (int cs = 0; cs < CS; cs++)
#pragma unroll
        for (int k = 0; k < 8; k++)
            dist[k] += g_dp[((size_t)(cs * 8 + k)) * NPIX + pix];

    const float rv = rp[0];
    float mx = -rv * dist[0];
#pragma unroll
    for (int k = 1; k < 8; k++) mx = fmaxf(mx, -rv * dist[k]);
    float m[8], sum = 0.f;
#pragma unroll
    for (int k = 0; k < 8; k++) {
        m[k] = exp2f((-rv * dist[k] - mx) * 1.4426950408889634f);
        sum += m[k];
    }
    const float inv = 1.f / sum;
#pragma unroll
    for (int k = 0; k < 8; k++) g_m[(size_t)k * NPIX + pix] = m[k] * inv;
}

// ---------------------------------------------------------------------------
// Kernel 2c: weighted aggregation + residual, barrier-free, channel-split.
// Same geometry as dist_kernel; m held in registers across the channel loop.
// ---------------------------------------------------------------------------
__global__ __launch_bounds__(256)
void agg2_kernel(const float* __restrict__ x, float* __restrict__ out) {
    const int b    = blockIdx.y;
    const int cs   = blockIdx.z;
    const int h    = blockIdx.x * 8 + (threadIdx.x >> 5);
    const int lane = threadIdx.x & 31;
    const int hm = max(h - 1, 0), hp = min(h + 1, Hh - 1);
    const size_t pix = (size_t)b * HW + h * Ww + lane * 4;

    float mk[8][4];
#pragma unroll
    for (int k = 0; k < 8; k++) {
        float4 t = *(const float4*)&g_m[(size_t)k * NPIX + pix];
        mk[k][0] = t.x; mk[k][1] = t.y; mk[k][2] = t.z; mk[k][3] = t.w;
    }

    const float* fb = g_feat1 + ((size_t)b * Cc + cs * CPS) * HW;
    const float* xb = x       + ((size_t)b * Cc + cs * CPS) * HW;
    float* ob       = out     + ((size_t)b * Cc + cs * CPS) * HW;

#pragma unroll 2
    for (int c = 0; c < CPS; c++) {
        const float* pl = fb + (size_t)c * HW;
        float4 vm = *(const float4*)(pl + hm * Ww + lane * 4);
        float4 v0 = *(const float4*)(pl + h  * Ww + lane * 4);
        float4 vp = *(const float4*)(pl + hp * Ww + lane * 4);
        float lm = __shfl_up_sync(0xffffffffu, vm.w, 1); if (lane == 0) lm = vm.x;
        float l0 = __shfl_up_sync(0xffffffffu, v0.w, 1); if (lane == 0) l0 = v0.x;
        float lp = __shfl_up_sync(0xffffffffu, vp.w, 1); if (lane == 0) lp = vp.x;
        float rm = __shfl_down_sync(0xffffffffu, vm.x, 1); if (lane == 31) rm = vm.w;
        float r0 = __shfl_down_sync(0xffffffffu, v0.x, 1); if (lane == 31) r0 = v0.w;
        float rp = __shfl_down_sync(0xffffffffu, vp.x, 1); if (lane == 31) rp = vp.w;
        float tm[6] = {lm, vm.x, vm.y, vm.z, vm.w, rm};
        float t0[6] = {l0, v0.x, v0.y, v0.z, v0.w, r0};
        float tp[6] = {lp, vp.x, vp.y, vp.z, vp.w, rp};

        float4 xv = *(const float4*)(xb + (size_t)c * HW + h * Ww + lane * 4);
        float xa[4] = {xv.x, xv.y, xv.z, xv.w};
        float o[4];
#pragma unroll
        for (int i = 0; i < 4; i++) {
            float a;
            a = mk[0][i] * tm[i];
            a = fmaf(mk[1][i], tm[i + 1], a);
            a = fmaf(mk[2][i], tm[i + 2], a);
            a = fmaf(mk[3][i], t0[i],     a);
            a = fmaf(mk[4][i], t0[i + 2], a);
            a = fmaf(mk[5][i], tp[i],     a);
            a = fmaf(mk[6][i], tp[i + 1], a);
            a = fmaf(mk[7][i], tp[i + 2], a);
            o[i] = a + xa[i];
        }
        *(float4*)(ob + (size_t)c * HW + h * Ww + lane * 4) =
            make_float4(o[0], o[1], o[2], o[3]);
    }
}

// ---------------------------------------------------------------------------
// Kernel 3: per-channel batch statistics -> scale/shift
// ---------------------------------------------------------------------------
__global__ __launch_bounds__(256)
void stats_kernel(const float* __restrict__ out,
                  const float* __restrict__ gamma,
                  const float* __restrict__ beta) {
    const int c = blockIdx.x;
    const int tid = threadIdx.x;
    float sum = 0.f, sq = 0.f;
#pragma unroll
    for (int b = 0; b < Bb; b++) {
        const float4* p = (const float4*)(out + ((size_t)b * Cc + c) * HW);
        for (int i = tid; i < HW / 4; i += 256) {
            float4 v = p[i];
            sum += (v.x + v.y) + (v.z + v.w);
            sq = fmaf(v.x, v.x, sq);
            sq = fmaf(v.y, v.y, sq);
            sq = fmaf(v.z, v.z, sq);
            sq = fmaf(v.w, v.w, sq);
        }
    }
    __shared__ float s1[8], s2[8];
    int lane = tid & 31, wid = tid >> 5;
#pragma unroll
    for (int o = 16; o > 0; o >>= 1) {
        sum += __shfl_xor_sync(0xffffffff, sum, o);
        sq  += __shfl_xor_sync(0xffffffff, sq, o);
    }
    if (lane == 0) { s1[wid] = sum; s2[wid] = sq; }
    __syncthreads();
    if (tid == 0) {
        float S = 0.f, Q = 0.f;
#pragma unroll
        for (int i = 0; i < 8; i++) { S += s1[i]; Q += s2[i]; }
        const float n = (float)(Bb * HW);
        float mean = S / n;
        float var  = Q / n - mean * mean;
        float istd = rsqrtf(var + 1e-5f);
        float sc   = istd * gamma[c];
        g_scale[c] = sc;
        g_shift[c] = beta[c] - mean * sc;
    }
}

// ---------------------------------------------------------------------------
// Kernel 4: in-place BN apply + LeakyReLU
// ---------------------------------------------------------------------------
__global__ __launch_bounds__(256)
void bnact_kernel(float* __restrict__ out) {
    int i4 = blockIdx.x * 256 + threadIdx.x;
    int c  = ((i4 * 4) >> 14) & (Cc - 1);
    float sc = g_scale[c], sh = g_shift[c];
    float4 v = ((float4*)out)[i4];
    v.x = fmaf(v.x, sc, sh); v.x = fmaxf(v.x, 0.01f * v.x);
    v.y = fmaf(v.y, sc, sh); v.y = fmaxf(v.y, 0.01f * v.y);
    v.z = fmaf(v.z, sc, sh); v.z = fmaxf(v.z, 0.01f * v.z);
    v.w = fmaf(v.w, sc, sh); v.w = fmaxf(v.w, 0.01f * v.w);
    ((float4*)out)[i4] = v;
}

// ---------------------------------------------------------------------------
extern "C" void kernel_launch(void* const* d_in, const int* in_sizes, int n_in,
                              void* d_out, int out_size) {
    const float* x     = (const float*)d_in[0];
    const float* W1    = (const float*)d_in[1];
    const float* b1    = (const float*)d_in[2];
    const float* r     = (const float*)d_in[3];
    const float* gamma = (const float*)d_in[4];
    const float* beta  = (const float*)d_in[5];
    float* out = (float*)d_out;

    cudaFuncSetAttribute(gemm_mma_kernel,
                         cudaFuncAttributeMaxDynamicSharedMemorySize, GSMEM);

    // 0) bf16 splits
    prep_w_kernel<<<Cc * Cc / 256, 256>>>(W1);
    prep_x_kernel<<<dim3(HW / 32, Cc / 32, Bb), dim3(32, 8)>>>(x);
    // 1) feat1 = W1 @ x + b1  (HMMA bf16 3-product)
    gemm_mma_kernel<<<dim3(HW / 128, Cc / 128, Bb), 256, GSMEM>>>(b1);
    // 2a) partial L1 distances (channel-split, barrier-free)
    dist_kernel<<<dim3(Hh / 8, Bb, CS), 256>>>();
    // 2b) reduce + softmax -> weights
    weights_kernel<<<NPIX / 256, 256>>>(r);
    // 2c) weighted aggregation + residual -> out
    agg2_kernel<<<dim3(Hh / 8, Bb, CS), 256>>>(x, out);
    // 3) batch statistics per channel
    stats_kernel<<<Cc, 256>>>(out, gamma, beta);
    // 4) BN + LeakyReLU in place
    bnact_kernel<<<TOTAL / 4 / 256, 256>>>(out);
}

// round 16
// speedup vs baseline: 1.5836x; 1.0282x over previous
#include <cuda_runtime.h>
#include <cuda_bf16.h>
#include <cstdint>

#define Hh 128
#define Ww 128
#define Cc 256
#define Bb 4
#define HW (Hh*Ww)            // 16384
#define TOTAL (Bb*Cc*HW)      // 16777216
#define NPIX (Bb*HW)          // 65536
#define CS 8                  // channel splits
#define CPS (Cc/CS)           // 32 channels per split

__device__ float g_feat1[TOTAL];               // feat1 = conv1x1(x), fp32 [b][c][p]
__device__ __nv_bfloat16 g_xt_hi[TOTAL];       // x transposed+split: [b][p][c]
__device__ __nv_bfloat16 g_xt_lo[TOTAL];
__device__ __nv_bfloat16 g_Whi[Cc*Cc];         // bf16 split of W1 [o][c]
__device__ __nv_bfloat16 g_Wlo[Cc*Cc];
__device__ float g_dp[CS*8*NPIX];              // partial L1 dists [cs][k][pix]
__device__ float g_m[8*NPIX];                  // softmax weights [k][pix]
__device__ float g_sp[Cc*8*2];                 // BN partials [c][slot][{sum,sq}]
__device__ float g_scale[Cc];
__device__ float g_shift[Cc];

// ---------------------------------------------------------------------------
// helpers (baseline PTX only)
// ---------------------------------------------------------------------------
__device__ __forceinline__ uint32_t smem_u32(const void* p) {
    uint32_t a;
    asm("{ .reg .u64 t; cvta.to.shared.u64 t, %1; cvt.u32.u64 %0, t; }"
        : "=r"(a) : "l"(p));
    return a;
}
__device__ __forceinline__ void cp_async16(uint32_t dst, const void* src) {
    asm volatile("cp.async.cg.shared.global [%0], [%1], 16;"
                 :: "r"(dst), "l"(src) : "memory");
}
__device__ __forceinline__ void mma16816(float* d, const uint32_t* a,
                                         const uint32_t* b) {
    asm volatile(
        "mma.sync.aligned.m16n8k16.row.col.f32.bf16.bf16.f32 "
        "{%0,%1,%2,%3}, {%4,%5,%6,%7}, {%8,%9}, {%0,%1,%2,%3};"
        : "+f"(d[0]), "+f"(d[1]), "+f"(d[2]), "+f"(d[3])
        : "r"(a[0]), "r"(a[1]), "r"(a[2]), "r"(a[3]), "r"(b[0]), "r"(b[1]));
}

// ---------------------------------------------------------------------------
// prep_w: bf16 hi/lo split of W1
// ---------------------------------------------------------------------------
__global__ void prep_w_kernel(const float* __restrict__ W1) {
    int i = blockIdx.x * 256 + threadIdx.x;
    float w = W1[i];
    __nv_bfloat16 hi = __float2bfloat16_rn(w);
    __nv_bfloat16 lo = __float2bfloat16_rn(w - __bfloat162float(hi));
    g_Whi[i] = hi;
    g_Wlo[i] = lo;
}

// ---------------------------------------------------------------------------
// prep_x: transpose [b][c][p] -> [b][p][c] and bf16 hi/lo split
// ---------------------------------------------------------------------------
__global__ __launch_bounds__(256)
void prep_x_kernel(const float* __restrict__ x) {
    __shared__ float s[32][33];
    const int b  = blockIdx.z;
    const int c0 = blockIdx.y * 32;
    const int p0 = blockIdx.x * 32;
    const int tx = threadIdx.x, ty = threadIdx.y;
#pragma unroll
    for (int i = 0; i < 4; i++) {
        int c = ty + i * 8;
        s[c][tx] = x[((size_t)b * Cc + c0 + c) * HW + p0 + tx];
    }
    __syncthreads();
#pragma unroll
    for (int i = 0; i < 4; i++) {
        int p = ty + i * 8;
        float v = s[tx][p];
        __nv_bfloat16 hi = __float2bfloat16_rn(v);
        __nv_bfloat16 lo = __float2bfloat16_rn(v - __bfloat162float(hi));
        size_t off = ((size_t)b * HW + p0 + p) * Cc + c0 + tx;
        g_xt_hi[off] = hi;
        g_xt_lo[off] = lo;
    }
}

// ---------------------------------------------------------------------------
// GEMM via mma.sync bf16 3-product split (HMMA), fp32 accumulate in regs.
// ---------------------------------------------------------------------------
#define ROWB   80
#define TILEB  (128*ROWB)
#define BUFB   (4*TILEB)
#define GSMEM  (2*BUFB)

__global__ __launch_bounds__(256, 2)
void gemm_mma_kernel(const float* __restrict__ b1) {
    extern __shared__ char smc[];
    const uint32_t sbase = smem_u32(smc);
    const int tid  = threadIdx.x;
    const int wid  = tid >> 5, lane = tid & 31;
    const int gid  = lane >> 2, tg = lane & 3;
    const int p0   = blockIdx.x * 128;
    const int m0   = blockIdx.y * 128;
    const int b    = blockIdx.z;
    const int mrow = (wid >> 1) * 32;
    const int ncol = (wid & 1) * 64;

    float acc[2][8][4];
#pragma unroll
    for (int mt = 0; mt < 2; mt++)
#pragma unroll
        for (int nt = 0; nt < 8; nt++)
#pragma unroll
            for (int j = 0; j < 4; j++) acc[mt][nt][j] = 0.f;

    auto stage = [&](int kc, int buf) {
        uint32_t bb = sbase + buf * BUFB;
        const int cidx0 = kc * 32;
#pragma unroll
        for (int it = 0; it < 8; it++) {
            int id  = tid + it * 256;
            int t   = id >> 9;
            int row = (id >> 2) & 127;
            int seg = id & 3;
            uint32_t dst = bb + t * TILEB + row * ROWB + seg * 16;
            int cidx = cidx0 + seg * 8;
            const __nv_bfloat16* src;
            if (t == 0)      src = g_Whi  + (size_t)(m0 + row) * Cc + cidx;
            else if (t == 1) src = g_Wlo  + (size_t)(m0 + row) * Cc + cidx;
            else if (t == 2) src = g_xt_hi + ((size_t)b * HW + p0 + row) * Cc + cidx;
            else             src = g_xt_lo + ((size_t)b * HW + p0 + row) * Cc + cidx;
            cp_async16(dst, src);
        }
        asm volatile("cp.async.commit_group;" ::: "memory");
    };

    stage(0, 0);

    for (int kc = 0; kc < 8; kc++) {
        if (kc < 7) stage(kc + 1, (kc + 1) & 1);
        if (kc < 7) asm volatile("cp.async.wait_group 1;" ::: "memory");
        else        asm volatile("cp.async.wait_group 0;" ::: "memory");
        __syncthreads();

        const char* base = smc + (kc & 1) * BUFB;
#pragma unroll
        for (int s = 0; s < 2; s++) {
            const int kb = s * 32;
            uint32_t ah[2][4], al[2][4];
#pragma unroll
            for (int mt = 0; mt < 2; mt++) {
                const char* ap = base + (mrow + mt * 16 + gid) * ROWB + kb + tg * 4;
                ah[mt][0] = *(const uint32_t*)(ap);
                ah[mt][1] = *(const uint32_t*)(ap + 8 * ROWB);
                ah[mt][2] = *(const uint32_t*)(ap + 16);
                ah[mt][3] = *(const uint32_t*)(ap + 8 * ROWB + 16);
                const char* ap2 = ap + TILEB;
                al[mt][0] = *(const uint32_t*)(ap2);
                al[mt][1] = *(const uint32_t*)(ap2 + 8 * ROWB);
                al[mt][2] = *(const uint32_t*)(ap2 + 16);
                al[mt][3] = *(const uint32_t*)(ap2 + 8 * ROWB + 16);
            }
#pragma unroll
            for (int nt = 0; nt < 8; nt++) {
                const char* bp = base + 2 * TILEB +
                                 (ncol + nt * 8 + gid) * ROWB + kb + tg * 4;
                uint32_t bh[2], bl[2];
                bh[0] = *(const uint32_t*)(bp);
                bh[1] = *(const uint32_t*)(bp + 16);
                mma16816(acc[0][nt], ah[0], bh);
                mma16816(acc[1][nt], ah[1], bh);
                mma16816(acc[0][nt], al[0], bh);
                mma16816(acc[1][nt], al[1], bh);
                const char* bp2 = bp + TILEB;
                bl[0] = *(const uint32_t*)(bp2);
                bl[1] = *(const uint32_t*)(bp2 + 16);
                mma16816(acc[0][nt], ah[0], bl);
                mma16816(acc[1][nt], ah[1], bl);
            }
        }
        __syncthreads();
    }

#pragma unroll
    for (int mt = 0; mt < 2; mt++) {
        int r0 = m0 + mrow + mt * 16 + gid;
        int r1 = r0 + 8;
        float bias0 = b1[r0], bias1 = b1[r1];
        float* o0 = g_feat1 + ((size_t)b * Cc + r0) * HW + p0 + ncol + tg * 2;
        float* o1 = g_feat1 + ((size_t)b * Cc + r1) * HW + p0 + ncol + tg * 2;
#pragma unroll
        for (int nt = 0; nt < 8; nt++) {
            float2 v0 = make_float2(acc[mt][nt][0] + bias0, acc[mt][nt][1] + bias0);
            float2 v1 = make_float2(acc[mt][nt][2] + bias1, acc[mt][nt][3] + bias1);
            *(float2*)(o0 + nt * 8) = v0;
            *(float2*)(o1 + nt * 8) = v1;
        }
    }
}

// ---------------------------------------------------------------------------
// Kernel 2a: partial L1 distances. Halos via scalar L1 loads (no shuffles —
// single-level load->compute dependency, full scoreboard overlap).
// grid (Hh/8, Bb, CS), block 256 = 8 rows x 32 lanes; 4 px/thread.
// OFFS: 0:(-1,-1) 1:(-1,0) 2:(-1,1) 3:(0,-1) 4:(0,1) 5:(1,-1) 6:(1,0) 7:(1,1)
// ---------------------------------------------------------------------------
__global__ __launch_bounds__(256)
void dist_kernel() {
    const int b    = blockIdx.y;
    const int cs   = blockIdx.z;
    const int h    = blockIdx.x * 8 + (threadIdx.x >> 5);
    const int lane = threadIdx.x & 31;
    const int hm = max(h - 1, 0), hp = min(h + 1, Hh - 1);
    const int w4 = lane * 4;
    const int wl = max(w4 - 1, 0);              // left halo col
    const int wr = min(w4 + 4, Ww - 1);         // right halo col
    const float* fb = g_feat1 + ((size_t)b * Cc + cs * CPS) * HW;

    float d[8][4];
#pragma unroll
    for (int k = 0; k < 8; k++)
#pragma unroll
        for (int i = 0; i < 4; i++) d[k][i] = 0.f;

#pragma unroll 2
    for (int c = 0; c < CPS; c++) {
        const float* rm_p = fb + (size_t)c * HW + hm * Ww;
        const float* r0_p = fb + (size_t)c * HW + h  * Ww;
        const float* rp_p = fb + (size_t)c * HW + hp * Ww;
        float4 vm = *(const float4*)(rm_p + w4);
        float4 v0 = *(const float4*)(r0_p + w4);
        float4 vp = *(const float4*)(rp_p + w4);
        float tm[6] = {rm_p[wl], vm.x, vm.y, vm.z, vm.w, rm_p[wr]};
        float t0[6] = {r0_p[wl], v0.x, v0.y, v0.z, v0.w, r0_p[wr]};
        float tp[6] = {rp_p[wl], vp.x, vp.y, vp.z, vp.w, rp_p[wr]};
#pragma unroll
        for (int i = 0; i < 4; i++) {
            float f0 = t0[i + 1];
            d[0][i] += fabsf(f0 - tm[i]);
            d[1][i] += fabsf(f0 - tm[i + 1]);
            d[2][i] += fabsf(f0 - tm[i + 2]);
            d[3][i] += fabsf(f0 - t0[i]);
            d[4][i] += fabsf(f0 - t0[i + 2]);
            d[5][i] += fabsf(f0 - tp[i]);
            d[6][i] += fabsf(f0 - tp[i + 1]);
            d[7][i] += fabsf(f0 - tp[i + 2]);
        }
    }

    const size_t pix = (size_t)b * HW + h * Ww + w4;
#pragma unroll
    for (int k = 0; k < 8; k++) {
        *(float4*)&g_dp[((size_t)(cs * 8 + k)) * NPIX + pix] =
            make_float4(d[k][0], d[k][1], d[k][2], d[k][3]);
    }
}

// ---------------------------------------------------------------------------
// Kernel 2b: reduce partials over CS, softmax -> weights m[k][pix]
// ---------------------------------------------------------------------------
__global__ __launch_bounds__(256)
void weights_kernel(const float* __restrict__ rp) {
    const int pix = blockIdx.x * 256 + threadIdx.x;
    float dist[8];
#pragma unroll
    for (int k = 0; k < 8; k++) dist[k] = 0.f;
#pragma unroll
    for (int cs = 0; cs < CS; cs++)
#pragma unroll
        for (int k = 0; k < 8; k++)
            dist[k] += g_dp[((size_t)(cs * 8 + k)) * NPIX + pix];

    const float rv = rp[0];
    float mx = -rv * dist[0];
#pragma unroll
    for (int k = 1; k < 8; k++) mx = fmaxf(mx, -rv * dist[k]);
    float m[8], sum = 0.f;
#pragma unroll
    for (int k = 0; k < 8; k++) {
        m[k] = exp2f((-rv * dist[k] - mx) * 1.4426950408889634f);
        sum += m[k];
    }
    const float inv = 1.f / sum;
#pragma unroll
    for (int k = 0; k < 8; k++) g_m[(size_t)k * NPIX + pix] = m[k] * inv;
}

// ---------------------------------------------------------------------------
// Kernel 2c: weighted aggregation + residual (halo loads, no shuffles)
// ---------------------------------------------------------------------------
__global__ __launch_bounds__(256)
void agg2_kernel(const float* __restrict__ x, float* __restrict__ out) {
    const int b    = blockIdx.y;
    const int cs   = blockIdx.z;
    const int h    = blockIdx.x * 8 + (threadIdx.x >> 5);
    const int lane = threadIdx.x & 31;
    const int hm = max(h - 1, 0), hp = min(h + 1, Hh - 1);
    const int w4 = lane * 4;
    const int wl = max(w4 - 1, 0);
    const int wr = min(w4 + 4, Ww - 1);
    const size_t pix = (size_t)b * HW + h * Ww + w4;

    float mk[8][4];
#pragma unroll
    for (int k = 0; k < 8; k++) {
        float4 t = *(const float4*)&g_m[(size_t)k * NPIX + pix];
        mk[k][0] = t.x; mk[k][1] = t.y; mk[k][2] = t.z; mk[k][3] = t.w;
    }

    const float* fb = g_feat1 + ((size_t)b * Cc + cs * CPS) * HW;
    const float* xb = x       + ((size_t)b * Cc + cs * CPS) * HW;
    float* ob       = out     + ((size_t)b * Cc + cs * CPS) * HW;

#pragma unroll 2
    for (int c = 0; c < CPS; c++) {
        const float* rm_p = fb + (size_t)c * HW + hm * Ww;
        const float* r0_p = fb + (size_t)c * HW + h  * Ww;
        const float* rp_p = fb + (size_t)c * HW + hp * Ww;
        float4 vm = *(const float4*)(rm_p + w4);
        float4 v0 = *(const float4*)(r0_p + w4);
        float4 vp = *(const float4*)(rp_p + w4);
        float tm[6] = {rm_p[wl], vm.x, vm.y, vm.z, vm.w, rm_p[wr]};
        float t0[6] = {r0_p[wl], v0.x, v0.y, v0.z, v0.w, r0_p[wr]};
        float tp[6] = {rp_p[wl], vp.x, vp.y, vp.z, vp.w, rp_p[wr]};

        float4 xv = *(const float4*)(xb + (size_t)c * HW + h * Ww + w4);
        float xa[4] = {xv.x, xv.y, xv.z, xv.w};
        float o[4];
#pragma unroll
        for (int i = 0; i < 4; i++) {
            float a;
            a = mk[0][i] * tm[i];
            a = fmaf(mk[1][i], tm[i + 1], a);
            a = fmaf(mk[2][i], tm[i + 2], a);
            a = fmaf(mk[3][i], t0[i],     a);
            a = fmaf(mk[4][i], t0[i + 2], a);
            a = fmaf(mk[5][i], tp[i],     a);
            a = fmaf(mk[6][i], tp[i + 1], a);
            a = fmaf(mk[7][i], tp[i + 2], a);
            o[i] = a + xa[i];
        }
        *(float4*)(ob + (size_t)c * HW + h * Ww + w4) =
            make_float4(o[0], o[1], o[2], o[3]);
    }
}

// ---------------------------------------------------------------------------
// Kernel 3a: BN partial sums. grid (Cc, 8): slot y covers b=y>>2? no:
// slot y -> batch b=y>>1, half=(y&1). Each block: 8192 floats.
// ---------------------------------------------------------------------------
__global__ __launch_bounds__(256)
void stats_part_kernel(const float* __restrict__ out) {
    const int c = blockIdx.x;
    const int y = blockIdx.y;                  // 0..7
    const int b = y >> 1, half = y & 1;
    const int tid = threadIdx.x;
    const float4* p = (const float4*)(out + ((size_t)b * Cc + c) * HW + half * (HW / 2));
    float sum = 0.f, sq = 0.f;
#pragma unroll
    for (int i = 0; i < 8; i++) {
        float4 v = p[tid + i * 256];
        sum += (v.x + v.y) + (v.z + v.w);
        sq = fmaf(v.x, v.x, sq);
        sq = fmaf(v.y, v.y, sq);
        sq = fmaf(v.z, v.z, sq);
        sq = fmaf(v.w, v.w, sq);
    }
    __shared__ float s1[8], s2[8];
    int lane = tid & 31, wid = tid >> 5;
#pragma unroll
    for (int o = 16; o > 0; o >>= 1) {
        sum += __shfl_xor_sync(0xffffffff, sum, o);
        sq  += __shfl_xor_sync(0xffffffff, sq, o);
    }
    if (lane == 0) { s1[wid] = sum; s2[wid] = sq; }
    __syncthreads();
    if (tid == 0) {
        float S = 0.f, Q = 0.f;
#pragma unroll
        for (int i = 0; i < 8; i++) { S += s1[i]; Q += s2[i]; }
        g_sp[(c * 8 + y) * 2 + 0] = S;
        g_sp[(c * 8 + y) * 2 + 1] = Q;
    }
}

// ---------------------------------------------------------------------------
// Kernel 3b: finalize scale/shift (1 block, 256 threads = 1/channel)
// ---------------------------------------------------------------------------
__global__ __launch_bounds__(256)
void stats_final_kernel(const float* __restrict__ gamma,
                        const float* __restrict__ beta) {
    const int c = threadIdx.x;
    float S = 0.f, Q = 0.f;
#pragma unroll
    for (int y = 0; y < 8; y++) {
        S += g_sp[(c * 8 + y) * 2 + 0];
        Q += g_sp[(c * 8 + y) * 2 + 1];
    }
    const float n = (float)(Bb * HW);
    float mean = S / n;
    float var  = Q / n - mean * mean;
    float istd = rsqrtf(var + 1e-5f);
    float sc   = istd * gamma[c];
    g_scale[c] = sc;
    g_shift[c] = beta[c] - mean * sc;
}

// ---------------------------------------------------------------------------
// Kernel 4: in-place BN apply + LeakyReLU
// ---------------------------------------------------------------------------
__global__ __launch_bounds__(256)
void bnact_kernel(float* __restrict__ out) {
    int i4 = blockIdx.x * 256 + threadIdx.x;
    int c  = ((i4 * 4) >> 14) & (Cc - 1);
    float sc = g_scale[c], sh = g_shift[c];
    float4 v = ((float4*)out)[i4];
    v.x = fmaf(v.x, sc, sh); v.x = fmaxf(v.x, 0.01f * v.x);
    v.y = fmaf(v.y, sc, sh); v.y = fmaxf(v.y, 0.01f * v.y);
    v.z = fmaf(v.z, sc, sh); v.z = fmaxf(v.z, 0.01f * v.z);
    v.w = fmaf(v.w, sc, sh); v.w = fmaxf(v.w, 0.01f * v.w);
    ((float4*)out)[i4] = v;
}

// ---------------------------------------------------------------------------
extern "C" void kernel_launch(void* const* d_in, const int* in_sizes, int n_in,
                              void* d_out, int out_size) {
    const float* x     = (const float*)d_in[0];
    const float* W1    = (const float*)d_in[1];
    const float* b1    = (const float*)d_in[2];
    const float* r     = (const float*)d_in[3];
    const float* gamma = (const float*)d_in[4];
    const float* beta  = (const float*)d_in[5];
    float* out = (float*)d_out;

    cudaFuncSetAttribute(gemm_mma_kernel,
                         cudaFuncAttributeMaxDynamicSharedMemorySize, GSMEM);

    // 0) bf16 splits
    prep_w_kernel<<<Cc * Cc / 256, 256>>>(W1);
    prep_x_kernel<<<dim3(HW / 32, Cc / 32, Bb), dim3(32, 8)>>>(x);
    // 1) feat1 = W1 @ x + b1  (HMMA bf16 3-product)
    gemm_mma_kernel<<<dim3(HW / 128, Cc / 128, Bb), 256, GSMEM>>>(b1);
    // 2a) partial L1 distances (channel-split, barrier-free, halo loads)
    dist_kernel<<<dim3(Hh / 8, Bb, CS), 256>>>();
    // 2b) reduce + softmax -> weights
    weights_kernel<<<NPIX / 256, 256>>>(r);
    // 2c) weighted aggregation + residual -> out
    agg2_kernel<<<dim3(Hh / 8, Bb, CS), 256>>>(x, out);
    // 3) batch statistics (partial + finalize)
    stats_part_kernel<<<dim3(Cc, 8), 256>>>(out);
    stats_final_kernel<<<1, 256>>>(gamma, beta);
    // 4) BN + LeakyReLU in place
    bnact_kernel<<<TOTAL / 4 / 256, 256>>>(out);
}